// round 14
// baseline (speedup 1.0000x reference)
#include <cuda_runtime.h>
#include <cstdint>

#define BB 256
#define TT 512
#define II 64
#define HH 512
#define OO 24

#define CLUSTER_NCTAS 8
#define NBLOCKS 128
#define NTHREADS 1024    // 32 warps; 8 per SMSP

#define BM 16     // batch rows per cluster
#define HC 64     // hidden cols per CTA (rank)

typedef unsigned long long u64;

// Hidden state ping-pong, b-major: g_h[parity][b][h]
__device__ float g_h[2][BB * HH];

// SMEM: Hs[16][128 float4] swizzled (32KB) + Xs[16][64] (4KB)
#define HS_F4 (BM * 128)
#define XS_F  (BM * II)
#define SMEM_BYTES (HS_F4 * 16 + XS_F * 4)   // 36864

#define FFMA2(acc, a, w) \
    asm("fma.rn.f32x2 %0, %1, %2, %0;" : "+l"(acc) : "l"(a), "l"(w))

__device__ __forceinline__ float4 ld_cg_v4(const float4* p) {
    float4 v;
    asm volatile("ld.global.cg.v4.f32 {%0,%1,%2,%3}, [%4];"
                 : "=f"(v.x), "=f"(v.y), "=f"(v.z), "=f"(v.w) : "l"(p) : "memory");
    return v;
}

__global__ void __launch_bounds__(NTHREADS, 1) __cluster_dims__(CLUSTER_NCTAS, 1, 1)
rnn_persistent_kernel(const float* __restrict__ x,
                      const float* __restrict__ W_ih,
                      const float* __restrict__ W_hh,
                      const float* __restrict__ b_ih,
                      const float* __restrict__ b_hh,
                      const float* __restrict__ fc_w,
                      const float* __restrict__ fc_b,
                      float* __restrict__ out)
{
    extern __shared__ float smem[];
    float4* Hs4 = (float4*)smem;              // [b][128 f4], piece-swizzled
    float*  Xs  = smem + HS_F4 * 4;           // [b][64]
    const u64* xq = (const u64*)Xs;

    const int tid  = threadIdx.x;
    const int lane = tid & 31;
    const int warp = tid >> 5;                // 0..31
    const int rank = blockIdx.x & (CLUSTER_NCTAS - 1);
    const int cl   = blockIdx.x >> 3;
    const int b0   = cl * BM;
    const int h0   = rank * HC;
    const int hw   = h0 + 2 * warp;           // warp's 2 h-columns
    const int k0   = lane * 16;               // lane's k-chunk
    const int i0   = lane * 2;                // lane's i-pair

    // ---- register-resident weights: 2 cols x 16 k per lane (36 regs) ----
    u64 whh[2][8];
    u64 wih[2];
    #pragma unroll
    for (int h = 0; h < 2; ++h) {
        const ulonglong2* wrow =
            (const ulonglong2*)&W_hh[(size_t)(hw + h) * HH + k0];
        #pragma unroll
        for (int j = 0; j < 4; ++j) {
            ulonglong2 v = wrow[j];
            whh[h][2 * j]     = v.x;
            whh[h][2 * j + 1] = v.y;
        }
        wih[h] = *(const u64*)&W_ih[(size_t)(hw + h) * II + i0];
    }
    const int h_idx = lane & 1;               // column this lane finishes with
    const float biasv = b_ih[hw + h_idx] + b_hh[hw + h_idx];

    // hoisted swizzled LDS base indices (loop-invariant)
    int sidx0 = (lane * 4 + 0) ^ ((lane >> 1) & 3);
    int sidx1 = (lane * 4 + 1) ^ ((lane >> 1) & 3);
    int sidx2 = (lane * 4 + 2) ^ ((lane >> 1) & 3);
    int sidx3 = (lane * 4 + 3) ^ ((lane >> 1) & 3);

    const float4* x4 = (const float4*)x;

    for (int t = 0; t < TT; ++t) {
        const float4* gprev4 = (const float4*)g_h[1 - (t & 1)];
        float*        gnew   = g_h[t & 1];

        // ---- stage x_t ----
        if (tid < 256) {
            int b = tid >> 4, i4 = tid & 15;
            ((float4*)Xs)[b * 16 + i4] =
                x4[((size_t)(b0 + b) * TT + t) * 16 + i4];
        }
        // ---- stage h_{t-1} (coalesced) into swizzled Hs ----
        if (t > 0) {
            #pragma unroll
            for (int n = 0; n < 2; ++n) {
                int idx = tid + n * NTHREADS;   // 0..2047
                int b = idx >> 7, p = idx & 127;
                float4 v = ld_cg_v4(gprev4 + (size_t)(b0 + b) * 128 + p);
                Hs4[b * 128 + (p ^ ((p >> 3) & 3))] = v;
            }
        }
        __syncthreads();

        const bool rec = (t > 0);

        #pragma unroll 8
        for (int b = 0; b < BM; ++b) {
            u64 acc0 = 0ull, acc1 = 0ull;

            // input projection: one i-pair per lane
            u64 ax = xq[b * 32 + lane];
            FFMA2(acc0, ax, wih[0]);
            FFMA2(acc1, ax, wih[1]);

            // recurrent: 4 swizzled conflict-free LDS.128 (imm offsets)
            if (rec) {
                const ulonglong2* hrow = (const ulonglong2*)(Hs4 + b * 128);
                ulonglong2 v0 = hrow[sidx0];
                ulonglong2 v1 = hrow[sidx1];
                ulonglong2 v2 = hrow[sidx2];
                ulonglong2 v3 = hrow[sidx3];
                FFMA2(acc0, v0.x, whh[0][0]);
                FFMA2(acc1, v0.x, whh[1][0]);
                FFMA2(acc0, v0.y, whh[0][1]);
                FFMA2(acc1, v0.y, whh[1][1]);
                FFMA2(acc0, v1.x, whh[0][2]);
                FFMA2(acc1, v1.x, whh[1][2]);
                FFMA2(acc0, v1.y, whh[0][3]);
                FFMA2(acc1, v1.y, whh[1][3]);
                FFMA2(acc0, v2.x, whh[0][4]);
                FFMA2(acc1, v2.x, whh[1][4]);
                FFMA2(acc0, v2.y, whh[0][5]);
                FFMA2(acc1, v2.y, whh[1][5]);
                FFMA2(acc0, v3.x, whh[0][6]);
                FFMA2(acc1, v3.x, whh[1][6]);
                FFMA2(acc0, v3.y, whh[0][7]);
                FFMA2(acc1, v3.y, whh[1][7]);
            }

            // unpack packed (even,odd) partials
            float s0, s1, e;
            asm("mov.b64 {%0,%1}, %2;" : "=f"(s0), "=f"(e) : "l"(acc0)); s0 += e;
            asm("mov.b64 {%0,%1}, %2;" : "=f"(s1), "=f"(e) : "l"(acc1)); s1 += e;

            // 5-shfl tree: lane ends with full sum of col hw + (lane&1)
            bool o1 = lane & 1;
            float k_ = o1 ? s1 : s0;
            float g_ = o1 ? s0 : s1;
            k_ += __shfl_xor_sync(0xffffffffu, g_, 1);
            k_ += __shfl_xor_sync(0xffffffffu, k_, 2);
            k_ += __shfl_xor_sync(0xffffffffu, k_, 4);
            k_ += __shfl_xor_sync(0xffffffffu, k_, 8);
            k_ += __shfl_xor_sync(0xffffffffu, k_, 16);

            if (lane < 2)
                gnew[(size_t)(b0 + b) * HH + hw + h_idx] =
                    fmaxf(k_ + biasv, 0.f);
        }

        // ---- cluster barrier (release h stores; acquire peers') ----
        asm volatile("fence.acq_rel.cluster;" ::: "memory");
        asm volatile("barrier.cluster.arrive.aligned;" ::: "memory");
        asm volatile("barrier.cluster.wait.aligned;"   ::: "memory");
    }

    // ---- fused FC epilogue ----
    {
        const float4* gl4 = (const float4*)g_h[(TT - 1) & 1];
        #pragma unroll
        for (int n = 0; n < 2; ++n) {
            int idx = tid + n * NTHREADS;
            int b = idx >> 7, p = idx & 127;
            float4 v = ld_cg_v4(gl4 + (size_t)(b0 + b) * 128 + p);
            Hs4[b * 128 + (p ^ ((p >> 3) & 3))] = v;
        }
        __syncthreads();

        if (rank == 0 && warp < 16) {
            float4 hp[4];
            #pragma unroll
            for (int i = 0; i < 4; ++i) {
                int p = lane + 32 * i;
                hp[i] = Hs4[warp * 128 + (p ^ ((p >> 3) & 3))];
            }
            #pragma unroll 4
            for (int o = 0; o < OO; ++o) {
                const float4* w4 = (const float4*)(fc_w + (size_t)o * HH);
                float s = 0.f;
                #pragma unroll
                for (int i = 0; i < 4; ++i) {
                    float4 wv = __ldg(&w4[lane + 32 * i]);
                    s = fmaf(hp[i].x, wv.x, s);
                    s = fmaf(hp[i].y, wv.y, s);
                    s = fmaf(hp[i].z, wv.z, s);
                    s = fmaf(hp[i].w, wv.w, s);
                }
                #pragma unroll
                for (int d = 16; d > 0; d >>= 1)
                    s += __shfl_xor_sync(0xffffffffu, s, d);
                if (lane == 0)
                    out[(size_t)(b0 + warp) * OO + o] = s + fc_b[o];
            }
        }
    }
}

extern "C" void kernel_launch(void* const* d_in, const int* in_sizes, int n_in,
                              void* d_out, int out_size)
{
    const float* x    = (const float*)d_in[0];
    const float* W_ih = (const float*)d_in[1];
    const float* W_hh = (const float*)d_in[2];
    const float* b_ih = (const float*)d_in[3];
    const float* b_hh = (const float*)d_in[4];
    const float* fc_w = (const float*)d_in[5];
    const float* fc_b = (const float*)d_in[6];
    int nb = 0;
    for (int i = 0; i < n_in; ++i) {
        const float* p = (const float*)d_in[i];
        switch (in_sizes[i]) {
            case BB * TT * II: x    = p; break;
            case HH * II:      W_ih = p; break;
            case HH * HH:      W_hh = p; break;
            case OO * HH:      fc_w = p; break;
            case OO:           fc_b = p; break;
            case HH:           if (nb++ == 0) b_ih = p; else b_hh = p; break;
            default: break;
        }
    }
    float* out = (float*)d_out;

    cudaFuncSetAttribute(rnn_persistent_kernel,
                         cudaFuncAttributeMaxDynamicSharedMemorySize, SMEM_BYTES);
    rnn_persistent_kernel<<<NBLOCKS, NTHREADS, SMEM_BYTES>>>(
        x, W_ih, W_hh, b_ih, b_hh, fc_w, fc_b, out);
}

// round 15
// speedup vs baseline: 1.9976x; 1.9976x over previous
#include <cuda_runtime.h>
#include <cuda_bf16.h>
#include <cstdint>

#define BB 256
#define TT 512
#define II 64
#define HH 512
#define OO 24

#define CLUSTER_NCTAS 8
#define NBLOCKS 128
#define NTHREADS 512

#define BM 16       // batch rows per cluster
#define HC 64       // hidden cols per CTA (rank)
#define K2T 288     // (512 + 64)/2 packed k-pairs (h || x)
#define SA 24       // As2 row stride (u32) per k2  — conflict-free a-frags
#define SBS 72      // Bs row stride (u32) per k2   — conflict-free b-frags

// u32 offsets in dynamic smem
#define OFF_AH 0
#define OFF_AL (K2T * SA)                 // 6912
#define OFF_BH (2 * K2T * SA)             // 13824
#define OFF_BL (OFF_BH + K2T * SBS)       // 34560
#define OFF_DR (OFF_BL + K2T * SBS)       // 55296  (Dred: 64 cols x 20)
#define OFF_BI (OFF_DR + 64 * 20)         // 56576  (bias fp32 x 64)
#define SMEM_U32 (OFF_BI + 64)            // 56640
#define SMEM_BYTES (SMEM_U32 * 4)         // 226560

typedef unsigned int u32;

// Hidden state ping-pong, packed split-bf16, k2-major: [k2:256][b:256]
__device__ u32 g_hh[2][256 * 256];
__device__ u32 g_hl[2][256 * 256];

// pack two floats to bf16x2 (x -> low 16, y -> high 16)
__device__ __forceinline__ u32 pack2(float x, float y) {
    u32 r;
    asm("{.reg .b16 lo, hi;\n\t"
        "cvt.rn.bf16.f32 lo, %1;\n\t"
        "cvt.rn.bf16.f32 hi, %2;\n\t"
        "mov.b32 %0, {lo, hi};}" : "=r"(r) : "f"(x), "f"(y));
    return r;
}
__device__ __forceinline__ float blo(u32 u) {
    __nv_bfloat16_raw r; r.x = (unsigned short)(u & 0xffffu);
    return __bfloat162float(*(__nv_bfloat16*)&r);
}
__device__ __forceinline__ float bhi(u32 u) {
    __nv_bfloat16_raw r; r.x = (unsigned short)(u >> 16);
    return __bfloat162float(*(__nv_bfloat16*)&r);
}
// split v into bf16 hi part (returned as float) for lo computation
__device__ __forceinline__ float bf16_rnd(float v) {
    return __bfloat162float(__float2bfloat16_rn(v));
}

__device__ __forceinline__ void mma_bf16(float& d0, float& d1, float& d2, float& d3,
                                         u32 a0, u32 a1, u32 a2, u32 a3,
                                         u32 b0, u32 b1) {
    asm("mma.sync.aligned.m16n8k16.row.col.f32.bf16.bf16.f32 "
        "{%0,%1,%2,%3}, {%4,%5,%6,%7}, {%8,%9}, {%0,%1,%2,%3};"
        : "+f"(d0), "+f"(d1), "+f"(d2), "+f"(d3)
        : "r"(a0), "r"(a1), "r"(a2), "r"(a3), "r"(b0), "r"(b1));
}

__global__ void __launch_bounds__(NTHREADS, 1) __cluster_dims__(CLUSTER_NCTAS, 1, 1)
rnn_persistent_kernel(const float* __restrict__ x,
                      const float* __restrict__ W_ih,
                      const float* __restrict__ W_hh,
                      const float* __restrict__ b_ih,
                      const float* __restrict__ b_hh,
                      const float* __restrict__ fc_w,
                      const float* __restrict__ fc_b,
                      float* __restrict__ out)
{
    extern __shared__ u32 sm[];
    u32* AH = sm + OFF_AH;
    u32* AL = sm + OFF_AL;
    u32* BH = sm + OFF_BH;
    u32* BL = sm + OFF_BL;
    float* DR = (float*)(sm + OFF_DR);
    float* BI = (float*)(sm + OFF_BI);

    const int tid  = threadIdx.x;
    const int lane = tid & 31;
    const int warp = tid >> 5;                 // 0..15
    const int wk   = warp >> 3;                // K-half
    const int wn   = warp & 7;                 // N-group (8 cols)
    const int g    = lane >> 2;                // 0..7
    const int q    = lane & 3;                 // 0..3
    const int rank = blockIdx.x & (CLUSTER_NCTAS - 1);
    const int cl   = blockIdx.x >> 3;
    const int b0   = cl * BM;
    const int h0   = rank * HC;

    // ---- one-time: zero A arrays, stage split weights, bias ----
    for (int u = tid; u < 2 * K2T * SA; u += NTHREADS) sm[u] = 0;
    for (int u = tid; u < K2T * 64; u += NTHREADS) {
        int n = u & 63, k2 = u >> 6;
        float2 w;
        if (k2 < 256)
            w = *(const float2*)&W_hh[(size_t)(h0 + n) * HH + 2 * k2];
        else
            w = *(const float2*)&W_ih[(size_t)(h0 + n) * II + 2 * (k2 - 256)];
        float xh = bf16_rnd(w.x), yh = bf16_rnd(w.y);
        BH[k2 * SBS + n] = pack2(w.x, w.y);
        BL[k2 * SBS + n] = pack2(w.x - xh, w.y - yh);
    }
    if (tid < 64) BI[tid] = b_ih[h0 + tid] + b_hh[h0 + tid];
    __syncthreads();

    const int c0 = (8 * wn + 2 * q) * 20;      // Dred base for this lane's cols

    for (int t = 0; t < TT; ++t) {
        const int par = t & 1;

        // ---- stage x_t (split) : A cols k2 = 256..287 ----
        {
            int b = tid >> 5, i2 = tid & 31;
            float2 v = *(const float2*)&x[((size_t)(b0 + b) * TT + t) * II + 2 * i2];
            float xh = bf16_rnd(v.x), yh = bf16_rnd(v.y);
            AH[(256 + i2) * SA + b] = pack2(v.x, v.y);
            AL[(256 + i2) * SA + b] = pack2(v.x - xh, v.y - yh);
        }
        // ---- stage h_{t-1}: pure packed copy (64KB) ----
        if (t > 0) {
            const float4* sH = (const float4*)g_hh[1 - par];
            const float4* sL = (const float4*)g_hl[1 - par];
            #pragma unroll
            for (int n = 0; n < 4; ++n) {
                int idx = tid + n * NTHREADS;          // 0..2047
                int a = idx >> 10, r = idx & 1023;
                int k2 = r >> 2, bq = r & 3;
                float4 v = (a ? sL : sH)[k2 * 64 + (b0 >> 2) + bq];
                ((float4*)(a ? AL : AH))[6 * k2 + bq] = v;
            }
        }
        __syncthreads();

        // ---- MMA: D[16 x 8] over this warp's K-half (18 slices of k16) ----
        float d0 = 0.f, d1 = 0.f, d2 = 0.f, d3 = 0.f;
        {
            int r0 = (8 * (18 * wk) + q) * SA;
            int w0 = (8 * (18 * wk) + q) * SBS + 8 * wn + g;
            #pragma unroll
            for (int s = 0; s < 18; ++s) {
                u32 a0h = AH[r0 + g], a1h = AH[r0 + g + 8];
                u32 a2h = AH[r0 + 96 + g], a3h = AH[r0 + 96 + g + 8];
                u32 a0l = AL[r0 + g], a1l = AL[r0 + g + 8];
                u32 a2l = AL[r0 + 96 + g], a3l = AL[r0 + 96 + g + 8];
                u32 b0h = BH[w0], b1h = BH[w0 + 4 * SBS];
                u32 b0l = BL[w0], b1l = BL[w0 + 4 * SBS];
                mma_bf16(d0, d1, d2, d3, a0h, a1h, a2h, a3h, b0h, b1h);
                mma_bf16(d0, d1, d2, d3, a0h, a1h, a2h, a3h, b0l, b1l);
                mma_bf16(d0, d1, d2, d3, a0l, a1l, a2l, a3l, b0h, b1h);
                r0 += 8 * SA;
                w0 += 8 * SBS;
            }
        }

        // ---- combine K-halves: wk1 stores partials, wk0 reduces+publishes ----
        if (wk == 1) {
            DR[c0 + g]          = d0;
            DR[c0 + 20 + g]     = d1;
            DR[c0 + g + 8]      = d2;
            DR[c0 + 20 + g + 8] = d3;
        }
        __syncthreads();
        if (wk == 0) {
            float bc0 = BI[8 * wn + 2 * q];
            float bc1 = BI[8 * wn + 2 * q + 1];
            float v0 = fmaxf(d0 + DR[c0 + g]          + bc0, 0.f);
            float v1 = fmaxf(d1 + DR[c0 + 20 + g]     + bc1, 0.f);
            float v2 = fmaxf(d2 + DR[c0 + g + 8]      + bc0, 0.f);
            float v3 = fmaxf(d3 + DR[c0 + 20 + g + 8] + bc1, 0.f);
            // split + pack + publish (k2-major, b contiguous)
            float h0v = bf16_rnd(v0), h1v = bf16_rnd(v1);
            float h2v = bf16_rnd(v2), h3v = bf16_rnd(v3);
            int k2o = (h0 >> 1) + 4 * wn + q;
            g_hh[par][k2o * 256 + b0 + g]     = pack2(v0, v1);
            g_hl[par][k2o * 256 + b0 + g]     = pack2(v0 - h0v, v1 - h1v);
            g_hh[par][k2o * 256 + b0 + g + 8] = pack2(v2, v3);
            g_hl[par][k2o * 256 + b0 + g + 8] = pack2(v2 - h2v, v3 - h3v);
        }

        // ---- cluster barrier (arrive = release of packed h stores) ----
        asm volatile("barrier.cluster.arrive.aligned;" ::: "memory");
        asm volatile("barrier.cluster.wait.aligned;"   ::: "memory");
    }

    // ---- fused FC epilogue: warp w handles batch row b0+w ----
    if (rank == 0) {
        const int parT = (TT - 1) & 1;
        const int b = b0 + warp;
        // lane loads its 8 k2 chunks of h_T (reconstruct fp32 = hi + lo)
        float hv[16];
        #pragma unroll
        for (int i = 0; i < 8; ++i) {
            int k2 = lane + 32 * i;
            u32 uh = g_hh[parT][k2 * 256 + b];
            u32 ul = g_hl[parT][k2 * 256 + b];
            hv[2 * i]     = blo(uh) + blo(ul);
            hv[2 * i + 1] = bhi(uh) + bhi(ul);
        }
        for (int o = 0; o < OO; ++o) {
            const float* wrow = fc_w + (size_t)o * HH;
            float s = 0.f;
            #pragma unroll
            for (int i = 0; i < 8; ++i) {
                int k2 = lane + 32 * i;
                float2 wv = *(const float2*)&wrow[2 * k2];
                s = fmaf(hv[2 * i], wv.x, s);
                s = fmaf(hv[2 * i + 1], wv.y, s);
            }
            #pragma unroll
            for (int d = 16; d > 0; d >>= 1)
                s += __shfl_xor_sync(0xffffffffu, s, d);
            if (lane == 0)
                out[(size_t)b * OO + o] = s + fc_b[o];
        }
    }
}

extern "C" void kernel_launch(void* const* d_in, const int* in_sizes, int n_in,
                              void* d_out, int out_size)
{
    const float* x    = (const float*)d_in[0];
    const float* W_ih = (const float*)d_in[1];
    const float* W_hh = (const float*)d_in[2];
    const float* b_ih = (const float*)d_in[3];
    const float* b_hh = (const float*)d_in[4];
    const float* fc_w = (const float*)d_in[5];
    const float* fc_b = (const float*)d_in[6];
    int nb = 0;
    for (int i = 0; i < n_in; ++i) {
        const float* p = (const float*)d_in[i];
        switch (in_sizes[i]) {
            case BB * TT * II: x    = p; break;
            case HH * II:      W_ih = p; break;
            case HH * HH:      W_hh = p; break;
            case OO * HH:      fc_w = p; break;
            case OO:           fc_b = p; break;
            case HH:           if (nb++ == 0) b_ih = p; else b_hh = p; break;
            default: break;
        }
    }
    float* out = (float*)d_out;

    cudaFuncSetAttribute(rnn_persistent_kernel,
                         cudaFuncAttributeMaxDynamicSharedMemorySize, SMEM_BYTES);
    rnn_persistent_kernel<<<NBLOCKS, NTHREADS, SMEM_BYTES>>>(
        x, W_ih, W_hh, b_ih, b_hh, fc_w, fc_b, out);
}

// round 16
// speedup vs baseline: 2.2944x; 1.1485x over previous
#include <cuda_runtime.h>
#include <cuda_bf16.h>
#include <cstdint>

#define BB 256
#define TT 512
#define II 64
#define HH 512
#define OO 24

#define CLUSTER_NCTAS 8
#define NBLOCKS 128
#define NTHREADS 512

#define BM 16
#define HC 64
#define K2T 288      // (512+64)/2 packed k-pairs (h || x)

// A: [buf:2][hi/lo][k2:288][b:16] u32, XOR-swizzled; per-buffer 9216 u32
#define ABUF 9216
#define ALO  4608
#define OFF_B  18432                   // BH 288*64, then BL
#define OFF_DR (OFF_B + 2 * 18432)     // 55296
#define OFF_BI (OFF_DR + 64 * 20)      // 56576
#define SMEM_U32 (OFF_BI + 64)         // 56640
#define SMEM_BYTES (SMEM_U32 * 4)      // 226560 (same as R15 — known to fit)

typedef unsigned int u32;

__device__ __forceinline__ u32 pack2(float x, float y) {
    u32 r;
    asm("{.reg .b16 lo, hi;\n\t"
        "cvt.rn.bf16.f32 lo, %1;\n\t"
        "cvt.rn.bf16.f32 hi, %2;\n\t"
        "mov.b32 %0, {lo, hi};}" : "=r"(r) : "f"(x), "f"(y));
    return r;
}
__device__ __forceinline__ float blo(u32 u) {
    __nv_bfloat16_raw r; r.x = (unsigned short)(u & 0xffffu);
    return __bfloat162float(*(__nv_bfloat16*)&r);
}
__device__ __forceinline__ float bhi(u32 u) {
    __nv_bfloat16_raw r; r.x = (unsigned short)(u >> 16);
    return __bfloat162float(*(__nv_bfloat16*)&r);
}
__device__ __forceinline__ float bf16_rnd(float v) {
    return __bfloat162float(__float2bfloat16_rn(v));
}
__device__ __forceinline__ u32 smem_u32p(const void* p) {
    u32 a;
    asm("{ .reg .u64 t; cvta.to.shared.u64 t, %1; cvt.u32.u64 %0, t; }"
        : "=r"(a) : "l"(p));
    return a;
}
__device__ __forceinline__ void mma_bf16(float& d0, float& d1, float& d2, float& d3,
                                         u32 a0, u32 a1, u32 a2, u32 a3,
                                         u32 b0, u32 b1) {
    asm("mma.sync.aligned.m16n8k16.row.col.f32.bf16.bf16.f32 "
        "{%0,%1,%2,%3}, {%4,%5,%6,%7}, {%8,%9}, {%0,%1,%2,%3};"
        : "+f"(d0), "+f"(d1), "+f"(d2), "+f"(d3)
        : "r"(a0), "r"(a1), "r"(a2), "r"(a3), "r"(b0), "r"(b1));
}

__global__ void __launch_bounds__(NTHREADS, 1) __cluster_dims__(CLUSTER_NCTAS, 1, 1)
rnn_persistent_kernel(const float* __restrict__ x,
                      const float* __restrict__ W_ih,
                      const float* __restrict__ W_hh,
                      const float* __restrict__ b_ih,
                      const float* __restrict__ b_hh,
                      const float* __restrict__ fc_w,
                      const float* __restrict__ fc_b,
                      float* __restrict__ out)
{
    extern __shared__ u32 sm[];
    u32*   B_H = sm + OFF_B;
    u32*   B_L = B_H + 18432;
    float* DR  = (float*)(sm + OFF_DR);
    float* BI  = (float*)(sm + OFF_BI);

    const int tid  = threadIdx.x;
    const int lane = tid & 31;
    const int warp = tid >> 5;             // 0..15
    const int wk   = warp >> 3;            // K-half
    const int wn   = warp & 7;             // N-group (8 cols)
    const int g    = lane >> 2;            // 0..7
    const int q    = lane & 3;             // 0..3
    const int rank = blockIdx.x & (CLUSTER_NCTAS - 1);
    const int cl   = blockIdx.x >> 3;
    const int b0   = cl * BM;
    const int h0   = rank * HC;

    // lane-constant swizzled offsets
    const int gs   = g ^ (8 * (q >> 1));          // A word offset (b=g)
    const int gsx  = gs ^ 8;                       // A word offset (b=g+8)
    const int colq = 8 * (wn ^ q) + g;             // B swizzled column

    // ---- one-time init: zero A (both buffers), stage split B, bias ----
    for (int u = tid; u < 2 * ABUF; u += NTHREADS) sm[u] = 0;
    for (int u = tid; u < K2T * 64; u += NTHREADS) {
        int n = u & 63, k2 = u >> 6;
        float2 w;
        if (k2 < 256)
            w = *(const float2*)&W_hh[(size_t)(h0 + n) * HH + 2 * k2];
        else
            w = *(const float2*)&W_ih[(size_t)(h0 + n) * II + 2 * (k2 - 256)];
        float xh = bf16_rnd(w.x), yh = bf16_rnd(w.y);
        int word = k2 * 64 + (n ^ (8 * (k2 & 3)));
        B_H[word] = pack2(w.x, w.y);
        B_L[word] = pack2(w.x - xh, w.y - yh);
    }
    if (tid < 64) BI[tid] = b_ih[h0 + tid] + b_hh[h0 + tid];

    // ---- stage x_0 into buffer 0 ----
    const int xb  = tid >> 5;              // batch row 0..15
    const int xi2 = tid & 31;              // i-pair 0..31
    const int xk2 = 256 + xi2;
    const int xword = xk2 * 16 + (xb ^ (8 * ((xi2 & 3) >> 1)));
    {
        float2 v = *(const float2*)&x[((size_t)(b0 + xb) * TT + 0) * II + 2 * xi2];
        float xh = bf16_rnd(v.x), yh = bf16_rnd(v.y);
        sm[xword]       = pack2(v.x, v.y);
        sm[ALO + xword] = pack2(v.x - xh, v.y - yh);
    }
    __syncthreads();
    // all CTAs initialized before any remote store may land
    asm volatile("barrier.cluster.arrive.aligned;" ::: "memory");
    asm volatile("barrier.cluster.wait.aligned;"   ::: "memory");

    // ---- mapa bases for the 8 peers (A region is at smem offset 0) ----
    u32 mp[8];
    {
        u32 base = smem_u32p(sm);
        #pragma unroll
        for (int p = 0; p < 8; ++p)
            asm("mapa.shared::cluster.u32 %0, %1, %2;"
                : "=r"(mp[p]) : "r"(base), "r"(p));
    }

    const int c0 = (8 * wn + 2 * q) * 20;   // DR base for this lane's cols

    for (int t = 0; t < TT; ++t) {
        const int buf  = t & 1;
        const int bufn = buf ^ 1;

        // prefetch x_{t+1} (consumed at end of step; latency hidden)
        float2 xv = make_float2(0.f, 0.f);
        if (t + 1 < TT)
            xv = *(const float2*)&x[((size_t)(b0 + xb) * TT + (t + 1)) * II + 2 * xi2];

        const u32* A_H = sm + buf * ABUF;
        const u32* A_L = A_H + ALO;

        // ---- MMA: D[16 x 8] over this warp's K-half (18 k16-slices) ----
        float d0 = 0.f, d1 = 0.f, d2 = 0.f, d3 = 0.f;
        {
            int ab = (8 * (18 * wk) + q) * 16;          // A word base (k2*16)
            int bb = (8 * (18 * wk) + q) * 64 + colq;   // B word base
            #pragma unroll
            for (int s = 0; s < 18; ++s) {
                u32 a0h = A_H[ab + gs],       a1h = A_H[ab + gsx];
                u32 a2h = A_H[ab + 64 + gs],  a3h = A_H[ab + 64 + gsx];
                u32 a0l = A_L[ab + gs],       a1l = A_L[ab + gsx];
                u32 a2l = A_L[ab + 64 + gs],  a3l = A_L[ab + 64 + gsx];
                u32 b0h = B_H[bb], b1h = B_H[bb + 256];
                u32 b0l = B_L[bb], b1l = B_L[bb + 256];
                mma_bf16(d0, d1, d2, d3, a0h, a1h, a2h, a3h, b0h, b1h);
                mma_bf16(d0, d1, d2, d3, a0h, a1h, a2h, a3h, b0l, b1l);
                mma_bf16(d0, d1, d2, d3, a0l, a1l, a2l, a3l, b0h, b1h);
                ab += 128;
                bb += 512;
            }
        }

        // ---- combine K-halves ----
        if (wk == 1) {
            DR[c0 + g]          = d0;
            DR[c0 + 20 + g]     = d1;
            DR[c0 + g + 8]      = d2;
            DR[c0 + 20 + g + 8] = d3;
        }
        __syncthreads();

        if (wk == 0) {
            float bc0 = BI[8 * wn + 2 * q];
            float bc1 = BI[8 * wn + 2 * q + 1];
            float v0 = fmaxf(d0 + DR[c0 + g]          + bc0, 0.f);
            float v1 = fmaxf(d1 + DR[c0 + 20 + g]     + bc1, 0.f);
            float v2 = fmaxf(d2 + DR[c0 + g + 8]      + bc0, 0.f);
            float v3 = fmaxf(d3 + DR[c0 + 20 + g + 8] + bc1, 0.f);

            float h0v = bf16_rnd(v0), h1v = bf16_rnd(v1);
            float h2v = bf16_rnd(v2), h3v = bf16_rnd(v3);
            u32 hh1 = pack2(v0, v1), hl1 = pack2(v0 - h0v, v1 - h1v);
            u32 hh2 = pack2(v2, v3), hl2 = pack2(v2 - h2v, v3 - h3v);

            const int k2o = rank * 32 + 4 * wn + q;     // k2&3 == q
            const u32 w1 = (u32)(k2o * 16 + gs) * 4;    // byte offsets
            const u32 w2 = (u32)(k2o * 16 + gsx) * 4;
            const u32 bo = (u32)(bufn * ABUF) * 4;
            #pragma unroll
            for (int p = 0; p < 8; ++p) {
                u32 r = mp[p] + bo;
                asm volatile("st.shared::cluster.u32 [%0], %1;"
                             :: "r"(r + w1), "r"(hh1) : "memory");
                asm volatile("st.shared::cluster.u32 [%0], %1;"
                             :: "r"(r + w2), "r"(hh2) : "memory");
                asm volatile("st.shared::cluster.u32 [%0], %1;"
                             :: "r"(r + (u32)(ALO * 4) + w1), "r"(hl1) : "memory");
                asm volatile("st.shared::cluster.u32 [%0], %1;"
                             :: "r"(r + (u32)(ALO * 4) + w2), "r"(hl2) : "memory");
            }
        }

        // ---- commit prefetched x_{t+1} into next buffer (local) ----
        if (t + 1 < TT) {
            u32* dst = sm + bufn * ABUF;
            float xh = bf16_rnd(xv.x), yh = bf16_rnd(xv.y);
            dst[xword]       = pack2(xv.x, xv.y);
            dst[ALO + xword] = pack2(xv.x - xh, xv.y - yh);
        }

        // ---- cluster barrier: arrive releases remote+local stores ----
        asm volatile("barrier.cluster.arrive.aligned;" ::: "memory");
        asm volatile("barrier.cluster.wait.aligned;"   ::: "memory");
    }

    // ---- fused FC epilogue: h_T sits in buffer 0 of every CTA ----
    if (rank == 0) {
        const int sw = 8 * ((lane & 3) >> 1);
        float hv[16];
        #pragma unroll
        for (int i = 0; i < 8; ++i) {
            int k2 = lane + 32 * i;
            int word = k2 * 16 + (warp ^ sw);
            u32 uh = sm[word];
            u32 ul = sm[ALO + word];
            hv[2 * i]     = blo(uh) + blo(ul);
            hv[2 * i + 1] = bhi(uh) + bhi(ul);
        }
        for (int o = 0; o < OO; ++o) {
            const float* wrow = fc_w + (size_t)o * HH;
            float s = 0.f;
            #pragma unroll
            for (int i = 0; i < 8; ++i) {
                int k2 = lane + 32 * i;
                float2 wv = *(const float2*)&wrow[2 * k2];
                s = fmaf(hv[2 * i], wv.x, s);
                s = fmaf(hv[2 * i + 1], wv.y, s);
            }
            #pragma unroll
            for (int d = 16; d > 0; d >>= 1)
                s += __shfl_xor_sync(0xffffffffu, s, d);
            if (lane == 0)
                out[(size_t)(b0 + warp) * OO + o] = s + fc_b[o];
        }
    }
}

extern "C" void kernel_launch(void* const* d_in, const int* in_sizes, int n_in,
                              void* d_out, int out_size)
{
    const float* x    = (const float*)d_in[0];
    const float* W_ih = (const float*)d_in[1];
    const float* W_hh = (const float*)d_in[2];
    const float* b_ih = (const float*)d_in[3];
    const float* b_hh = (const float*)d_in[4];
    const float* fc_w = (const float*)d_in[5];
    const float* fc_b = (const float*)d_in[6];
    int nb = 0;
    for (int i = 0; i < n_in; ++i) {
        const float* p = (const float*)d_in[i];
        switch (in_sizes[i]) {
            case BB * TT * II: x    = p; break;
            case HH * II:      W_ih = p; break;
            case HH * HH:      W_hh = p; break;
            case OO * HH:      fc_w = p; break;
            case OO:           fc_b = p; break;
            case HH:           if (nb++ == 0) b_ih = p; else b_hh = p; break;
            default: break;
        }
    }
    float* out = (float*)d_out;

    cudaFuncSetAttribute(rnn_persistent_kernel,
                         cudaFuncAttributeMaxDynamicSharedMemorySize, SMEM_BYTES);
    rnn_persistent_kernel<<<NBLOCKS, NTHREADS, SMEM_BYTES>>>(
        x, W_ih, W_hh, b_ih, b_hh, fc_w, fc_b, out);
}